// round 16
// baseline (speedup 1.0000x reference)
#include <cuda_runtime.h>
#include <cuda_bf16.h>
#include <cstdint>

#define E_ROWS 100000
#define TS 132   // padded row stride (floats) for fp32 activation buffers

typedef unsigned long long ull;

// ---- dynamic smem layout (bytes) ----
// Phase 1/2: emb fp32 tile at 0 (67584), h1 fp32 at OFF_ACT1, W packed at OFF_WP.
// GEMM2 epilogue writes A_hi/A_lo (bf16, 272B row stride) over the dead emb tile.
// GEMM3 B tiles (bf16 hi/lo) overwrite dead h1 + dead W region.
#define OFF_AHI  0
#define OFF_ALO  34816
#define OFF_ACT1 69632    // fp32 h1 [128][TS] = 67584 B
#define OFF_BHI  69632    // B hi: 160 rows x 272 B = 43520
#define OFF_BLO  113152   // B lo: 43520 (ends 156672, spills into dead W region)
#define OFF_WP   137216   // packed W0/W1: 65536 (ends 202752)
#define OFF_X2   202752   // 128*4 fp32 = 2048
#define SMEM_BYTES 204800

#define A_STRIDE 272      // 68 words; 68 mod 32 = 4 -> lane bank = 4g+c (conflict-free)
#define A_LO_DELTA 34816
#define B_LO_DELTA 43520

__device__ __forceinline__ void fma2(ull& d, ull a, ull b){
    asm("fma.rn.f32x2 %0,%1,%2,%0;" : "+l"(d) : "l"(a), "l"(b));
}
__device__ __forceinline__ float2 up2(ull v){
    float2 r; asm("mov.b64 {%0,%1},%2;" : "=f"(r.x), "=f"(r.y) : "l"(v)); return r;
}
__device__ __forceinline__ ull pk2(float x, float y){
    ull r; asm("mov.b64 %0,{%1,%2};" : "=l"(r) : "f"(x), "f"(y)); return r;
}
__device__ __forceinline__ float silu_f(float x){ return x / (1.0f + __expf(-x)); }

// m16n8k16 row.col bf16 -> f32 accumulate (sm_80+ baseline PTX; no arch gating)
__device__ __forceinline__ void mma_bf16(float* c, const uint32_t* a, const uint32_t* b){
    asm volatile("mma.sync.aligned.m16n8k16.row.col.f32.bf16.bf16.f32 "
        "{%0,%1,%2,%3}, {%4,%5,%6,%7}, {%8,%9}, {%0,%1,%2,%3};"
        : "+f"(c[0]), "+f"(c[1]), "+f"(c[2]), "+f"(c[3])
        : "r"(a[0]), "r"(a[1]), "r"(a[2]), "r"(a[3]), "r"(b[0]), "r"(b[1]));
}

// ---- fp32 f32x2 GEMM (proven since R9) ----
// out[r][c] = silu(scale * sum_k in[r][k] * W[k][c]); fp32 [128][TS] out
template<int KP>
__device__ __forceinline__ void gemm_act(const float* __restrict__ sIn,
                                         const ull* __restrict__ sWp,
                                         float* __restrict__ sOut,
                                         int tid, float scale)
{
    const int cg = tid & 31;
    const int r0 = (tid >> 5) * 8;
    ull acc[8][4];
    #pragma unroll
    for (int i = 0; i < 8; i++)
        #pragma unroll
        for (int j = 0; j < 4; j++) acc[i][j] = 0ull;

    #pragma unroll 2
    for (int kq = 0; kq < KP; kq += 2) {
        ull b0[4], b1[4];
        const ull* w0 = sWp + kq * 128 + cg;
        #pragma unroll
        for (int j = 0; j < 4; j++) { b0[j] = w0[32 * j]; b1[j] = w0[128 + 32 * j]; }
        #pragma unroll
        for (int h = 0; h < 2; h++) {
            ulonglong2 a2[4];
            #pragma unroll
            for (int i = 0; i < 4; i++)
                a2[i] = *(const ulonglong2*)(sIn + (r0 + 4 * h + i) * TS + 2 * kq);
            #pragma unroll
            for (int i = 0; i < 4; i++) {
                #pragma unroll
                for (int j = 0; j < 4; j++) fma2(acc[4 * h + i][j], a2[i].x, b0[j]);
                #pragma unroll
                for (int j = 0; j < 4; j++) fma2(acc[4 * h + i][j], a2[i].y, b1[j]);
            }
        }
    }
    #pragma unroll
    for (int i = 0; i < 8; i++)
        #pragma unroll
        for (int j = 0; j < 4; j++) {
            float2 p = up2(acc[i][j]);
            sOut[(r0 + i) * TS + cg + 32 * j] = silu_f((p.x + p.y) * scale);
        }
}

// GEMM2: same core; epilogue writes bf16 hi/lo h2 into [row][k] tiles, 272B stride.
__device__ __forceinline__ void gemm2_split(const float* __restrict__ sIn,
                                            const ull* __restrict__ sWp,
                                            char* __restrict__ smc,
                                            int tid, float scale)
{
    const int cg = tid & 31;
    const int r0 = (tid >> 5) * 8;
    ull acc[8][4];
    #pragma unroll
    for (int i = 0; i < 8; i++)
        #pragma unroll
        for (int j = 0; j < 4; j++) acc[i][j] = 0ull;

    #pragma unroll 2
    for (int kq = 0; kq < 64; kq += 2) {
        ull b0[4], b1[4];
        const ull* w0 = sWp + kq * 128 + cg;
        #pragma unroll
        for (int j = 0; j < 4; j++) { b0[j] = w0[32 * j]; b1[j] = w0[128 + 32 * j]; }
        #pragma unroll
        for (int h = 0; h < 2; h++) {
            ulonglong2 a2[4];
            #pragma unroll
            for (int i = 0; i < 4; i++)
                a2[i] = *(const ulonglong2*)(sIn + (r0 + 4 * h + i) * TS + 2 * kq);
            #pragma unroll
            for (int i = 0; i < 4; i++) {
                #pragma unroll
                for (int j = 0; j < 4; j++) fma2(acc[4 * h + i][j], a2[i].x, b0[j]);
                #pragma unroll
                for (int j = 0; j < 4; j++) fma2(acc[4 * h + i][j], a2[i].y, b1[j]);
            }
        }
    }
    #pragma unroll
    for (int i = 0; i < 8; i++)
        #pragma unroll
        for (int j = 0; j < 4; j++) {
            float2 p = up2(acc[i][j]);
            float v = silu_f((p.x + p.y) * scale);
            __nv_bfloat16 hi = __float2bfloat16(v);
            float lo = v - __bfloat162float(hi);
            int row = r0 + i, k = cg + 32 * j;
            uint32_t byte = (uint32_t)row * A_STRIDE + (uint32_t)k * 2u;
            *(__nv_bfloat16*)(smc + OFF_AHI + byte) = hi;
            *(__nv_bfloat16*)(smc + OFF_ALO + byte) = __float2bfloat16(lo);
        }
}

__global__ __launch_bounds__(512, 1)
void tpmlp_kernel(const float* __restrict__ emb, const float* __restrict__ x1,
                  const float* __restrict__ x2,  const float* __restrict__ W0,
                  const float* __restrict__ W1,  const float* __restrict__ P1,
                  const float* __restrict__ P2,  const float* __restrict__ P3,
                  const float* __restrict__ P4,  const float* __restrict__ P5,
                  float* __restrict__ out)
{
    extern __shared__ char smc[];
    float* sAct0 = (float*)(smc);             // emb fp32 tile (dies before A written)
    float* sAct1 = (float*)(smc + OFF_ACT1);  // h1 fp32
    ull*   sWp   = (ull*)  (smc + OFF_WP);
    float* sX2   = (float*)(smc + OFF_X2);

    const int tid  = threadIdx.x;
    const int wid  = tid >> 5;
    const int lane = tid & 31;
    const int row0 = blockIdx.x * 128;

    // --- stage emb tile [128][64] ---
    for (int idx = tid; idx < 128 * 16; idx += 512) {
        int r = idx >> 4, c4 = idx & 15;
        int gr = row0 + r;
        float4 v = make_float4(0.f, 0.f, 0.f, 0.f);
        if (gr < E_ROWS) v = ((const float4*)emb)[(size_t)gr * 16 + c4];
        *(float4*)(sAct0 + r * TS + c4 * 4) = v;
    }
    // --- stage W0 k-pair-packed ---
    for (int idx = tid; idx < 32 * 128; idx += 512) {
        int c = idx & 127, kp = idx >> 7;
        sWp[idx] = pk2(W0[2 * kp * 128 + c], W0[(2 * kp + 1) * 128 + c]);
    }
    // --- stage x2 [128][4] ---
    {
        int r = tid >> 2, gr = row0 + r;
        sX2[tid] = (gr < E_ROWS) ? x2[(size_t)gr * 4 + (tid & 3)] : 0.f;
    }
    __syncthreads();

    // h1 = silu(emb @ W0 / sqrt(64))
    gemm_act<32>(sAct0, sWp, sAct1, tid, 0.125f);
    __syncthreads();

    // --- stage W1 packed ---
    for (int idx = tid; idx < 64 * 128; idx += 512) {
        int c = idx & 127, kp = idx >> 7;
        sWp[idx] = pk2(W1[2 * kp * 128 + c], W1[(2 * kp + 1) * 128 + c]);
    }
    __syncthreads();

    // h2 = silu(h1 @ W1 / sqrt(128)) -> bf16 hi/lo A tiles (overwrites dead emb)
    gemm2_split(sAct1, sWp, smc, tid, 0.08838834764831845f);
    __syncthreads();   // A complete; h1 + W1 now dead

    const float* Pm[5] = {P1, P2, P3, P4, P5};
    const float SC = 0.08838834764831845f; // 1/sqrt(128)
    const float C0 = 0.7071067811865476f;  // 1/sqrt(2)
    const float C3 = 0.5773502691896258f;  // 1/sqrt(3)
    const float C6 = 0.4082482904638630f;  // 1/sqrt(6)

    // GEMM3 via mma.sync m16n8k16 bf16, 3x hi/lo split.
    // Warp w: m-tile = w>>1 (16 rows), u-sub = (w&1)*16 within the 32-u chunk.
    // B layout: n-row = m*32 + u  (all 5 m's for a given u land in the same lane).
    const int g  = lane >> 2;       // group id (rows / B n)
    const int c4 = lane & 3;        // k-pair id
    const int R    = (wid >> 1) * 16;
    const int usub = (wid & 1) * 16;
    const char* pA = smc + OFF_AHI + (uint32_t)(R + g) * A_STRIDE + 4u * c4;
    const char* pB = smc + OFF_BHI + (uint32_t)(usub + g) * A_STRIDE + 4u * c4;

    for (int ch = 0; ch < 2; ch++) {
        const int u0 = ch * 32;
        // --- stage B chunk: bf16 hi/lo, [n=m*32+u][k], 272B stride ---
        for (int idx = tid; idx < 5 * 32 * 128; idx += 512) {
            int u = idx & 31;
            int k = (idx >> 5) & 127;
            int m = idx >> 12;
            float v = Pm[m][k * 64 + u0 + u];
            uint32_t byte = (uint32_t)(m * 32 + u) * A_STRIDE + (uint32_t)k * 2u;
            __nv_bfloat16 hi = __float2bfloat16(v);
            *(__nv_bfloat16*)(smc + OFF_BHI + byte) = hi;
            *(__nv_bfloat16*)(smc + OFF_BLO + byte) = __float2bfloat16(v - __bfloat162float(hi));
        }
        __syncthreads();

        float acc[5][2][4];
        #pragma unroll
        for (int m = 0; m < 5; m++)
            #pragma unroll
            for (int jt = 0; jt < 2; jt++)
                #pragma unroll
                for (int r = 0; r < 4; r++) acc[m][jt][r] = 0.f;

        #pragma unroll
        for (int ks = 0; ks < 8; ks++) {
            const int ao = ks * 32;
            uint32_t ah[4], al[4];
            // A frag: a0={g,k2c}, a1={g+8,k2c}, a2={g,k2c+8}, a3={g+8,k2c+8}
            ah[0] = *(const uint32_t*)(pA + ao);
            ah[1] = *(const uint32_t*)(pA + ao + 8 * A_STRIDE);
            ah[2] = *(const uint32_t*)(pA + ao + 16);
            ah[3] = *(const uint32_t*)(pA + ao + 8 * A_STRIDE + 16);
            al[0] = *(const uint32_t*)(pA + A_LO_DELTA + ao);
            al[1] = *(const uint32_t*)(pA + A_LO_DELTA + ao + 8 * A_STRIDE);
            al[2] = *(const uint32_t*)(pA + A_LO_DELTA + ao + 16);
            al[3] = *(const uint32_t*)(pA + A_LO_DELTA + ao + 8 * A_STRIDE + 16);
            #pragma unroll
            for (int m = 0; m < 5; m++) {
                #pragma unroll
                for (int jt = 0; jt < 2; jt++) {
                    const char* pb = pB + (uint32_t)(m * 32 + jt * 8) * A_STRIDE + ao;
                    uint32_t bh[2], bl[2];
                    bh[0] = *(const uint32_t*)(pb);
                    bh[1] = *(const uint32_t*)(pb + 16);
                    bl[0] = *(const uint32_t*)(pb + B_LO_DELTA);
                    bl[1] = *(const uint32_t*)(pb + B_LO_DELTA + 16);
                    mma_bf16(acc[m][jt], ah, bh);
                    mma_bf16(acc[m][jt], ah, bl);
                    mma_bf16(acc[m][jt], al, bh);
                }
            }
        }

        // --- combine + writeout ---
        // acc[m][jt][2*rh + t] = w_m at row (R+g+8*rh), u = u0+usub+jt*8+2*c4+t
        #pragma unroll
        for (int rh = 0; rh < 2; rh++) {
            int lr = R + g + 8 * rh;
            int gr = row0 + lr;
            if (gr >= E_ROWS) continue;
            float x20 = sX2[lr * 4 + 0];
            float y0  = sX2[lr * 4 + 1];
            float y1  = sX2[lr * 4 + 2];
            float y2  = sX2[lr * 4 + 3];
            const float* x1r  = x1  + (size_t)gr * 256;
            float*       outr = out + (size_t)gr * 448;
            #pragma unroll
            for (int jt = 0; jt < 2; jt++) {
                #pragma unroll
                for (int t = 0; t < 2; t++) {
                    int u = u0 + usub + jt * 8 + 2 * c4 + t;
                    int r = 2 * rh + t;
                    float w1 = acc[0][jt][r] * SC;
                    float w2 = acc[1][jt][r] * SC;
                    float w3 = acc[2][jt][r] * SC;
                    float w4 = acc[3][jt][r] * SC;
                    float w5 = acc[4][jt][r] * SC;
                    float x10 = x1r[u];
                    float a0  = x1r[64 + 3 * u + 0];
                    float a1  = x1r[64 + 3 * u + 1];
                    float a2v = x1r[64 + 3 * u + 2];
                    float dt  = a0 * y0 + a1 * y1 + a2v * y2;
                    outr[u] = C0 * (w1 * x10 * x20 + w4 * dt * C3);
                    outr[64 + 3 * u + 0] = C0 * (w2 * a0  * x20 + w3 * x10 * y0);
                    outr[64 + 3 * u + 1] = C0 * (w2 * a1  * x20 + w3 * x10 * y1);
                    outr[64 + 3 * u + 2] = C0 * (w2 * a2v * x20 + w3 * x10 * y2);
                    outr[256 + 3 * u + 0] = C6 * w5 * (a1  * y2 - a2v * y1);
                    outr[256 + 3 * u + 1] = C6 * w5 * (a2v * y0 - a0  * y2);
                    outr[256 + 3 * u + 2] = C6 * w5 * (a0  * y1 - a1  * y0);
                }
            }
        }
        __syncthreads();  // all B reads done before restage
    }
}

extern "C" void kernel_launch(void* const* d_in, const int* in_sizes, int n_in,
                              void* d_out, int out_size)
{
    const float* emb = (const float*)d_in[0];
    const float* x1  = (const float*)d_in[1];
    const float* x2  = (const float*)d_in[2];
    const float* W0  = (const float*)d_in[3];
    const float* W1  = (const float*)d_in[4];
    const float* P1  = (const float*)d_in[5];
    const float* P2  = (const float*)d_in[6];
    const float* P3  = (const float*)d_in[7];
    const float* P4  = (const float*)d_in[8];
    const float* P5  = (const float*)d_in[9];
    float* out = (float*)d_out;

    cudaFuncSetAttribute(tpmlp_kernel, cudaFuncAttributeMaxDynamicSharedMemorySize, SMEM_BYTES);
    dim3 grid((E_ROWS + 127) / 128);  // 782 CTAs
    tpmlp_kernel<<<grid, 512, SMEM_BYTES>>>(emb, x1, x2, W0, W1, P1, P2, P3, P4, P5, out);
}